// round 9
// baseline (speedup 1.0000x reference)
#include <cuda_runtime.h>

// GRAPE: 20 commuting X-rotations collapse to one rotation, Theta = sum(a)*DT/2.
// 256 MiB pure stream at the mixed-R/W HBM roofline (~6.2 TB/s effective).
//
// R8 -> R9: contiguous pair-split (the 43.5us winner structure) + ILP=2
// WITHIN each pair: each thread front-batches 4 loads from its 2 read
// streams (chunks i and i+quarter), doubling MLP_p1 without adding stream
// fragmentation (unlike R2's 8-stream ILP=2 which regressed).
//
//   pair A: (r0, m1) -> out0r = c*r0 + s*m1 ; out1i = c*m1 - s*r0
//   pair B: (r1, m0) -> out1r = c*r1 + s*m0 ; out0i = c*m0 - s*r1

#define NUM_STEPS 20
#define DT_HALF   (0.5f * (1.0f / 20.0f))
#define BATCH     8388608

__global__ __launch_bounds__(256) void grape_kernel(
    const float* __restrict__ amps,
    const float* __restrict__ sr,
    const float* __restrict__ si,
    float* __restrict__ out)
{
    float theta = 0.0f;
#pragma unroll
    for (int k = 0; k < NUM_STEPS; k++) theta += __ldg(&amps[k]);
    theta *= DT_HALF;
    const float c = cosf(theta);
    const float s = sinf(theta);

    const int n4   = BATCH / 4;        // 2,097,152 float4 per row
    const int half = n4 / 2;           // per-pair thread count (ILP=2)
    const int tid  = blockIdx.x * blockDim.x + threadIdx.x;

    const float4* pa;
    const float4* pb;
    float4* po1;                       // c*a + s*b
    float4* po2;                       // c*b - s*a
    int i;

    if (tid < half) {
        // pair A: (r0, m1) -> out0r, out1i
        i   = tid;
        pa  = (const float4*)sr;                          // r0
        pb  = (const float4*)(si + (size_t)BATCH);        // m1
        po1 = (float4*)out;                               // out0r
        po2 = (float4*)(out + 3 * (size_t)BATCH);         // out1i
    } else {
        // pair B: (r1, m0) -> out1r, out0i
        i   = tid - half;
        pa  = (const float4*)(sr + (size_t)BATCH);        // r1
        pb  = (const float4*)si;                          // m0
        po1 = (float4*)(out + (size_t)BATCH);             // out1r
        po2 = (float4*)(out + 2 * (size_t)BATCH);         // out0i
    }
    const int j = i + half;            // second chunk, same 2 streams

    // Front-batch 4 loads (MLP=4 from 2 streams).
    float4 a0 = __ldg(&pa[i]);
    float4 b0 = __ldg(&pb[i]);
    float4 a1 = __ldg(&pa[j]);
    float4 b1 = __ldg(&pb[j]);

    float4 o1, o2;
    o1.x = fmaf(c, a0.x,  s * b0.x);  o2.x = fmaf(c, b0.x, -s * a0.x);
    o1.y = fmaf(c, a0.y,  s * b0.y);  o2.y = fmaf(c, b0.y, -s * a0.y);
    o1.z = fmaf(c, a0.z,  s * b0.z);  o2.z = fmaf(c, b0.z, -s * a0.z);
    o1.w = fmaf(c, a0.w,  s * b0.w);  o2.w = fmaf(c, b0.w, -s * a0.w);
    po1[i] = o1;
    po2[i] = o2;

    float4 p1, p2;
    p1.x = fmaf(c, a1.x,  s * b1.x);  p2.x = fmaf(c, b1.x, -s * a1.x);
    p1.y = fmaf(c, a1.y,  s * b1.y);  p2.y = fmaf(c, b1.y, -s * a1.y);
    p1.z = fmaf(c, a1.z,  s * b1.z);  p2.z = fmaf(c, b1.z, -s * a1.z);
    p1.w = fmaf(c, a1.w,  s * b1.w);  p2.w = fmaf(c, b1.w, -s * a1.w);
    po1[j] = p1;
    po2[j] = p2;
}

extern "C" void kernel_launch(void* const* d_in, const int* in_sizes, int n_in,
                              void* d_out, int out_size)
{
    const float* amps = (const float*)d_in[0];  // [20]
    const float* sr   = (const float*)d_in[1];  // [2, B]
    const float* si   = (const float*)d_in[2];  // [2, B]
    float* out        = (float*)d_out;          // [2, 2, B]

    const int n4 = BATCH / 4;
    const int threads = 256;
    const int blocks = n4 / threads;            // 8192 (2 pairs x ILP=2)
    grape_kernel<<<blocks, threads>>>(amps, sr, si, out);
}